// round 16
// baseline (speedup 1.0000x reference)
#include <cuda_runtime.h>
#include <cuda_fp16.h>
#include <cstdint>

// Problem constants
#define B_TOK   512
#define L_SEQ   50
#define T_TOK   (B_TOK * L_SEQ)   // 25600
#define D_IN    768
#define O_OUT   300
#define O_PAD   320
#define N_EXP   8

// Main GEMM tiling
#define MT      128                 // tokens per CTA (grid.x = 200)
#define NT      160                 // outputs per CTA (grid.y = 2)
#define KC      32                  // K elems per chunk
#define NCHUNK  (D_IN / KC)         // 24

// SMEM: stride 40 fp16 = 80 B rows (conflict-free ldmatrix)
#define RS      80
#define A_BYTES (MT * RS)           // 10240 (A_hi only)
#define B_BYTES (NT * RS)           // 12800 per expert per (hi|lo)
#define OFF_B   A_BYTES             // expert e: +e*2*B_BYTES, lo at +B_BYTES
#define OFF_G   (OFF_B + N_EXP * 2 * B_BYTES)     // 215040
#define SMEM_MAIN (OFF_G + MT * N_EXP * 4)        // 219136

// Scratch
__device__ float g_gates[T_TOK * N_EXP];
__device__ float g_gbw[(size_t)T_TOK * O_OUT];
__device__ __align__(16) __half g_xhi[(size_t)T_TOK * D_IN];
__device__ __align__(16) __half g_whi[(size_t)N_EXP * O_PAD * D_IN];
__device__ __align__(16) __half g_wlo[(size_t)N_EXP * O_PAD * D_IN];

// ---------------------------------------------------------------------------
// Helpers (baseline ISA only — sm_103 has no 'a' features)
// ---------------------------------------------------------------------------
__device__ __forceinline__ uint32_t smem_u32(const void* p) {
    uint32_t a;
    asm("{ .reg .u64 t; cvta.to.shared.u64 t, %1; cvt.u32.u64 %0, t; }"
        : "=r"(a) : "l"(p));
    return a;
}
__device__ __forceinline__ void ldsm_x4(uint32_t* r, uint32_t addr) {
    asm volatile("ldmatrix.sync.aligned.m8n8.x4.shared.b16 {%0,%1,%2,%3}, [%4];"
                 : "=r"(r[0]), "=r"(r[1]), "=r"(r[2]), "=r"(r[3]) : "r"(addr));
}
__device__ __forceinline__ void ldsm_x2(uint32_t* r, uint32_t addr) {
    asm volatile("ldmatrix.sync.aligned.m8n8.x2.shared.b16 {%0,%1}, [%2];"
                 : "=r"(r[0]), "=r"(r[1]) : "r"(addr));
}
__device__ __forceinline__ void mma_f16(float* d, const uint32_t* a, const uint32_t* b) {
    asm volatile(
        "mma.sync.aligned.m16n8k16.row.col.f32.f16.f16.f32 "
        "{%0,%1,%2,%3}, {%4,%5,%6,%7}, {%8,%9}, {%0,%1,%2,%3};"
        : "+f"(d[0]), "+f"(d[1]), "+f"(d[2]), "+f"(d[3])
        : "r"(a[0]), "r"(a[1]), "r"(a[2]), "r"(a[3]), "r"(b[0]), "r"(b[1]));
}
__device__ __forceinline__ void cp_async16(uint32_t dst, const void* src) {
    asm volatile("cp.async.cg.shared.global [%0], [%1], 16;"
                 :: "r"(dst), "l"(src) : "memory");
}
__device__ __forceinline__ void cp_commit_wait0() {
    asm volatile("cp.async.commit_group;" ::: "memory");
    asm volatile("cp.async.wait_group 0;" ::: "memory");
}
__device__ __forceinline__ uint32_t pack_half2(__half a, __half b) {
    __half2 h2(a, b);
    return *reinterpret_cast<uint32_t*>(&h2);
}

// ---------------------------------------------------------------------------
// Kernel 1: fused prologue — gates | pack_x(hi only) | pack_w(hi/lo)
// ---------------------------------------------------------------------------
#define NG   3200
#define NPX  19200
#define NPW  1920

__global__ __launch_bounds__(256) void prologue_kernel(
    const float* __restrict__ x, const float* __restrict__ w_gate,
    const float* __restrict__ expert_w)
{
    const int b = blockIdx.x;
    const int tid = threadIdx.x;

    if (b < NG) {
        int warp = b * 8 + (tid >> 5);
        int lane = tid & 31;
        const float* xr = x + (size_t)warp * D_IN;
        float z[N_EXP];
#pragma unroll
        for (int e = 0; e < N_EXP; e++) z[e] = 0.f;
        for (int i = lane; i < D_IN; i += 32) {
            float xv = xr[i];
            const float4* wg = reinterpret_cast<const float4*>(w_gate + (size_t)i * N_EXP);
            float4 w0 = wg[0], w1 = wg[1];
            z[0] += xv * w0.x; z[1] += xv * w0.y; z[2] += xv * w0.z; z[3] += xv * w0.w;
            z[4] += xv * w1.x; z[5] += xv * w1.y; z[6] += xv * w1.z; z[7] += xv * w1.w;
        }
#pragma unroll
        for (int e = 0; e < N_EXP; e++) {
#pragma unroll
            for (int off = 16; off; off >>= 1)
                z[e] += __shfl_xor_sync(0xffffffffu, z[e], off);
        }
        float m = z[0];
#pragma unroll
        for (int e = 1; e < N_EXP; e++) m = fmaxf(m, z[e]);
        float s = 0.f, p[N_EXP];
#pragma unroll
        for (int e = 0; e < N_EXP; e++) { p[e] = expf(z[e] - m); s += p[e]; }
        float inv = 1.f / s;
        if (lane < N_EXP) g_gates[(size_t)warp * N_EXP + lane] = p[lane] * inv;
    } else if (b < NG + NPX) {
        // ---- pack x -> fp16 hi (residual dropped by 2-pass scheme) ----
        size_t i4 = (size_t)(b - NG) * 256 + tid;
        float4 v = reinterpret_cast<const float4*>(x)[i4];
        __half h0 = __float2half_rn(v.x), h1 = __float2half_rn(v.y);
        __half h2 = __float2half_rn(v.z), h3 = __float2half_rn(v.w);
        reinterpret_cast<uint2*>(g_xhi)[i4] = make_uint2(pack_half2(h0, h1), pack_half2(h2, h3));
    } else {
        // ---- pack expert_w -> fp16 hi/lo, O padded 300 -> 320 ----
        size_t i4 = (size_t)(b - NG - NPX) * 256 + tid;
        size_t idx = i4 * 4;
        int e = (int)(idx / ((size_t)O_PAD * D_IN));
        size_t rem = idx % ((size_t)O_PAD * D_IN);
        int o = (int)(rem / D_IN);
        int k = (int)(rem % D_IN);
        float4 v = make_float4(0.f, 0.f, 0.f, 0.f);
        if (o < O_OUT)
            v = *reinterpret_cast<const float4*>(
                expert_w + ((size_t)e * O_OUT + o) * D_IN + k);
        __half h0 = __float2half_rn(v.x), h1 = __float2half_rn(v.y);
        __half h2 = __float2half_rn(v.z), h3 = __float2half_rn(v.w);
        __half l0 = __float2half_rn(v.x - __half2float(h0));
        __half l1 = __float2half_rn(v.y - __half2float(h1));
        __half l2 = __float2half_rn(v.z - __half2float(h2));
        __half l3 = __float2half_rn(v.w - __half2float(h3));
        reinterpret_cast<uint2*>(g_whi)[i4] = make_uint2(pack_half2(h0, h1), pack_half2(h2, h3));
        reinterpret_cast<uint2*>(g_wlo)[i4] = make_uint2(pack_half2(l0, l1), pack_half2(l2, l3));
    }
}

// ---------------------------------------------------------------------------
// Kernel 2: fused bw + gbw (unchanged — exact fp32 path)
// ---------------------------------------------------------------------------
#define OCH 75
__global__ __launch_bounds__(256) void bw_gbw_kernel(
    const float* __restrict__ expert_bias, const float* __restrict__ expert_w)
{
    const int l = blockIdx.x;
    const int ob4 = blockIdx.y * OCH;
    const int tid = threadIdx.x;

    __shared__ float sbias[N_EXP][D_IN];
    __shared__ float sbw[N_EXP][OCH + 1];

    for (int i = tid; i < N_EXP * D_IN / 4; i += 256) {
        int e = i / (D_IN / 4), kk = i % (D_IN / 4);
        float4 v = *reinterpret_cast<const float4*>(
            expert_bias + ((size_t)e * L_SEQ + l) * D_IN + kk * 4);
        *reinterpret_cast<float4*>(&sbias[e][kk * 4]) = v;
    }
    __syncthreads();

    for (int i = tid; i < N_EXP * OCH; i += 256) {
        int e = i / OCH, oo = i % OCH;
        const float* wr = expert_w + ((size_t)e * O_OUT + ob4 + oo) * D_IN;
        float s = 0.f;
#pragma unroll 4
        for (int k = 0; k < D_IN; k += 4) {
            float4 w4 = *reinterpret_cast<const float4*>(wr + k);
            s += sbias[e][k] * w4.x + sbias[e][k + 1] * w4.y
               + sbias[e][k + 2] * w4.z + sbias[e][k + 3] * w4.w;
        }
        sbw[e][oo] = s;
    }
    __syncthreads();

    for (int i = tid; i < B_TOK * OCH; i += 256) {
        int bb = i / OCH, oo = i % OCH;
        int t = bb * L_SEQ + l;
        const float4* gp = reinterpret_cast<const float4*>(g_gates + (size_t)t * N_EXP);
        float4 ga = gp[0], gb = gp[1];
        float s = ga.x * sbw[0][oo] + ga.y * sbw[1][oo]
                + ga.z * sbw[2][oo] + ga.w * sbw[3][oo]
                + gb.x * sbw[4][oo] + gb.y * sbw[5][oo]
                + gb.z * sbw[6][oo] + gb.w * sbw[7][oo];
        g_gbw[(size_t)t * O_OUT + ob4 + oo] = s;
    }
}

// ---------------------------------------------------------------------------
// Kernel 3: main GEMM. 512 threads, 16 warps (4M x 4N), warp tile 32M x 40N.
// fp16 2-pass: dd_e = Ah*(Bh + Bl); fold once per (expert, chunk).
// ---------------------------------------------------------------------------
extern __shared__ unsigned char dsmem[];

__global__ __launch_bounds__(512, 1) void moe_hmma_kernel(float* __restrict__ out)
{
    const int tid  = threadIdx.x;
    const int lane = tid & 31;
    const int wid  = tid >> 5;
    const int wm   = wid & 3;
    const int wn   = wid >> 2;
    const int tb   = blockIdx.x * MT;
    const int ob   = blockIdx.y * NT;

    const uint32_t sb   = smem_u32(dsmem);
    const uint32_t A_hi = sb;
    const uint32_t Bbas = sb + OFF_B;
    float* sg = reinterpret_cast<float*>(dsmem + OFF_G);

    const uint32_t laneA  = (uint32_t)(((lane & 7) + ((lane >> 3) & 1) * 8) * RS
                                       + ((lane >> 4) & 1) * 16);
    const uint32_t laneB4 = (uint32_t)(((lane & 7) + ((lane >> 4) & 1) * 8) * RS
                                       + ((lane >> 3) & 1) * 16);
    const int li = lane & 15;
    const uint32_t laneB2 = (uint32_t)((li & 7) * RS + (li >> 3) * 16);

    const int grp  = lane >> 2;
    const int rofs = wm * 32 + grp;

    // stage gates [128 x 8] to smem
#pragma unroll
    for (int t = 0; t < 2; t++) {
        int i = tid + t * 512;
        sg[i] = g_gates[(size_t)(tb + (i >> 3)) * N_EXP + (i & 7)];
    }

    float outacc[2][5][4];
#pragma unroll
    for (int i = 0; i < 2; i++)
#pragma unroll
        for (int j = 0; j < 5; j++)
#pragma unroll
            for (int q = 0; q < 4; q++) outacc[i][j][q] = 0.f;

    for (int c = 0; c < NCHUNK; c++) {
        const int c0 = c * KC;
        __syncthreads();   // previous chunk's compute done (covers sg on c=0)

        // ---- stage A_hi: 1 uint4 per thread ----
        {
            int row = tid >> 2, c8 = tid & 3;
            cp_async16(A_hi + (uint32_t)(row * RS + c8 * 16),
                       g_xhi + (size_t)(tb + row) * D_IN + c0 + c8 * 8);
        }
        // ---- stage B hi/lo for 8 experts: 20 uint4 per thread ----
#pragma unroll
        for (int t = 0; t < 20; t++) {
            int i = tid + t * 512;
            int e = i / 1280;
            int rem = i - e * 1280;
            int lohalf = rem >= 640;
            int rr = lohalf ? rem - 640 : rem;
            int r = rr >> 2, c8 = rr & 3;
            const __half* src = lohalf ? g_wlo : g_whi;
            cp_async16(Bbas + (uint32_t)(e * (2 * B_BYTES) + lohalf * B_BYTES
                                         + r * RS + c8 * 16),
                       src + ((size_t)e * O_PAD + ob + r) * D_IN + c0 + c8 * 8);
        }
        cp_commit_wait0();
        __syncthreads();

#pragma unroll 1
        for (int e = 0; e < N_EXP; e++) {
            const uint32_t Bh = Bbas + (uint32_t)(e * (2 * B_BYTES));
            const uint32_t Bl = Bh + B_BYTES;

            float dd[2][5][4];
#pragma unroll
            for (int i = 0; i < 2; i++)
#pragma unroll
                for (int j = 0; j < 5; j++)
#pragma unroll
                    for (int q = 0; q < 4; q++) dd[i][j][q] = 0.f;

#pragma unroll
            for (int ks = 0; ks < 2; ks++) {
                uint32_t ah[2][4];
#pragma unroll
                for (int mi = 0; mi < 2; mi++)
                    ldsm_x4(ah[mi], A_hi + laneA
                            + (uint32_t)((wm * 32 + mi * 16) * RS + ks * 32));

                const uint32_t bo4a = laneB4 + (uint32_t)((wn * 40) * RS + ks * 32);
                const uint32_t bo4b = laneB4 + (uint32_t)((wn * 40 + 16) * RS + ks * 32);
                const uint32_t bo2  = laneB2 + (uint32_t)((wn * 40 + 32) * RS + ks * 32);

                uint32_t b4a[4], b4b[4], b2[2];
                // pass 0: Ah * Bh
                ldsm_x4(b4a, Bh + bo4a);
                ldsm_x4(b4b, Bh + bo4b);
                ldsm_x2(b2,  Bh + bo2);
#pragma unroll
                for (int mi = 0; mi < 2; mi++) {
                    mma_f16(dd[mi][0], ah[mi], b4a);
                    mma_f16(dd[mi][1], ah[mi], b4a + 2);
                    mma_f16(dd[mi][2], ah[mi], b4b);
                    mma_f16(dd[mi][3], ah[mi], b4b + 2);
                    mma_f16(dd[mi][4], ah[mi], b2);
                }
                // pass 1: Ah * Bl (reuse regs)
                ldsm_x4(b4a, Bl + bo4a);
                ldsm_x4(b4b, Bl + bo4b);
                ldsm_x2(b2,  Bl + bo2);
#pragma unroll
                for (int mi = 0; mi < 2; mi++) {
                    mma_f16(dd[mi][0], ah[mi], b4a);
                    mma_f16(dd[mi][1], ah[mi], b4a + 2);
                    mma_f16(dd[mi][2], ah[mi], b4b);
                    mma_f16(dd[mi][3], ah[mi], b4b + 2);
                    mma_f16(dd[mi][4], ah[mi], b2);
                }
            }

            // ---- fold once per (expert, chunk): outacc += g * dd ----
            float g0 = sg[(rofs)      * N_EXP + e];
            float g1 = sg[(rofs + 8)  * N_EXP + e];
            float g2 = sg[(rofs + 16) * N_EXP + e];
            float g3 = sg[(rofs + 24) * N_EXP + e];
#pragma unroll
            for (int nt = 0; nt < 5; nt++) {
                outacc[0][nt][0] += g0 * dd[0][nt][0];
                outacc[0][nt][1] += g0 * dd[0][nt][1];
                outacc[0][nt][2] += g1 * dd[0][nt][2];
                outacc[0][nt][3] += g1 * dd[0][nt][3];
                outacc[1][nt][0] += g2 * dd[1][nt][0];
                outacc[1][nt][1] += g2 * dd[1][nt][1];
                outacc[1][nt][2] += g3 * dd[1][nt][2];
                outacc[1][nt][3] += g3 * dd[1][nt][3];
            }
        }
    }

    // ---- epilogue: out = outacc - gbw ----
#pragma unroll
    for (int mi = 0; mi < 2; mi++) {
        const int t0 = tb + rofs + mi * 16;
#pragma unroll
        for (int nt = 0; nt < 5; nt++) {
            const int o = ob + wn * 40 + nt * 8 + (lane & 3) * 2;
            if (o < O_OUT) {
                {
                    const float2 gb = *reinterpret_cast<const float2*>(
                        g_gbw + (size_t)t0 * O_OUT + o);
                    float2 w = make_float2(outacc[mi][nt][0] - gb.x,
                                           outacc[mi][nt][1] - gb.y);
                    *reinterpret_cast<float2*>(out + (size_t)t0 * O_OUT + o) = w;
                }
                {
                    const int t1 = t0 + 8;
                    const float2 gb = *reinterpret_cast<const float2*>(
                        g_gbw + (size_t)t1 * O_OUT + o);
                    float2 w = make_float2(outacc[mi][nt][2] - gb.x,
                                           outacc[mi][nt][3] - gb.y);
                    *reinterpret_cast<float2*>(out + (size_t)t1 * O_OUT + o) = w;
                }
            }
        }
    }
}

// ---------------------------------------------------------------------------
extern "C" void kernel_launch(void* const* d_in, const int* in_sizes, int n_in,
                              void* d_out, int out_size)
{
    const float* x           = (const float*)d_in[0];
    const float* w_gate      = (const float*)d_in[1];
    const float* expert_w    = (const float*)d_in[2];
    const float* expert_bias = (const float*)d_in[3];
    float* out = (float*)d_out;
    (void)in_sizes; (void)n_in; (void)out_size;

    cudaFuncSetAttribute(moe_hmma_kernel,
                         cudaFuncAttributeMaxDynamicSharedMemorySize, SMEM_MAIN);

    prologue_kernel<<<NG + NPX + NPW, 256>>>(x, w_gate, expert_w);
    bw_gbw_kernel<<<dim3(L_SEQ, O_OUT / OCH), 256>>>(expert_bias, expert_w);
    moe_hmma_kernel<<<dim3(T_TOK / MT, O_PAD / NT), 512, SMEM_MAIN>>>(out);
}

// round 17
// speedup vs baseline: 2.1937x; 2.1937x over previous
#include <cuda_runtime.h>
#include <cuda_fp16.h>
#include <cstdint>

// Problem constants
#define B_TOK   512
#define L_SEQ   50
#define T_TOK   (B_TOK * L_SEQ)   // 25600
#define D_IN    768
#define O_OUT   300
#define O_PAD   320
#define N_EXP   8

// Main GEMM tiling
#define MT      128                 // tokens per CTA (grid.x = 200)
#define NT      160                 // outputs per CTA (grid.y = 2)
#define KC      32                  // K elems per chunk
#define NCHUNK  (D_IN / KC)         // 24

// SMEM: stride 40 fp16 = 80 B rows (conflict-free ldmatrix)
#define RS      80
#define A_BYTES (MT * RS)           // 10240 (A_hi only)
#define B_BYTES (NT * RS)           // 12800 per expert (hi only)
#define OFF_B   A_BYTES             // expert e at +e*B_BYTES
#define OFF_G   (OFF_B + N_EXP * B_BYTES)         // 112640
#define SMEM_MAIN (OFF_G + MT * N_EXP * 4)        // 116736

// Scratch
__device__ float g_gates[T_TOK * N_EXP];
__device__ float g_gbw[(size_t)T_TOK * O_OUT];
__device__ __align__(16) __half g_xhi[(size_t)T_TOK * D_IN];
__device__ __align__(16) __half g_whi[(size_t)N_EXP * O_PAD * D_IN];

// ---------------------------------------------------------------------------
// Helpers (baseline ISA only — sm_103 has no 'a' features)
// ---------------------------------------------------------------------------
__device__ __forceinline__ uint32_t smem_u32(const void* p) {
    uint32_t a;
    asm("{ .reg .u64 t; cvta.to.shared.u64 t, %1; cvt.u32.u64 %0, t; }"
        : "=r"(a) : "l"(p));
    return a;
}
__device__ __forceinline__ void ldsm_x4(uint32_t* r, uint32_t addr) {
    asm volatile("ldmatrix.sync.aligned.m8n8.x4.shared.b16 {%0,%1,%2,%3}, [%4];"
                 : "=r"(r[0]), "=r"(r[1]), "=r"(r[2]), "=r"(r[3]) : "r"(addr));
}
__device__ __forceinline__ void ldsm_x2(uint32_t* r, uint32_t addr) {
    asm volatile("ldmatrix.sync.aligned.m8n8.x2.shared.b16 {%0,%1}, [%2];"
                 : "=r"(r[0]), "=r"(r[1]) : "r"(addr));
}
__device__ __forceinline__ void mma_f16(float* d, const uint32_t* a, const uint32_t* b) {
    asm volatile(
        "mma.sync.aligned.m16n8k16.row.col.f32.f16.f16.f32 "
        "{%0,%1,%2,%3}, {%4,%5,%6,%7}, {%8,%9}, {%0,%1,%2,%3};"
        : "+f"(d[0]), "+f"(d[1]), "+f"(d[2]), "+f"(d[3])
        : "r"(a[0]), "r"(a[1]), "r"(a[2]), "r"(a[3]), "r"(b[0]), "r"(b[1]));
}
__device__ __forceinline__ void cp_async16(uint32_t dst, const void* src) {
    asm volatile("cp.async.cg.shared.global [%0], [%1], 16;"
                 :: "r"(dst), "l"(src) : "memory");
}
__device__ __forceinline__ void cp_commit_wait0() {
    asm volatile("cp.async.commit_group;" ::: "memory");
    asm volatile("cp.async.wait_group 0;" ::: "memory");
}
__device__ __forceinline__ uint32_t pack_half2(__half a, __half b) {
    __half2 h2(a, b);
    return *reinterpret_cast<uint32_t*>(&h2);
}

// ---------------------------------------------------------------------------
// Kernel 1: fused prologue — gates | pack_x(fp16) | pack_w(fp16 hi only)
// ---------------------------------------------------------------------------
#define NG   3200
#define NPX  19200
#define NPW  1920

__global__ __launch_bounds__(256) void prologue_kernel(
    const float* __restrict__ x, const float* __restrict__ w_gate,
    const float* __restrict__ expert_w)
{
    const int b = blockIdx.x;
    const int tid = threadIdx.x;

    if (b < NG) {
        int warp = b * 8 + (tid >> 5);
        int lane = tid & 31;
        const float* xr = x + (size_t)warp * D_IN;
        float z[N_EXP];
#pragma unroll
        for (int e = 0; e < N_EXP; e++) z[e] = 0.f;
        for (int i = lane; i < D_IN; i += 32) {
            float xv = xr[i];
            const float4* wg = reinterpret_cast<const float4*>(w_gate + (size_t)i * N_EXP);
            float4 w0 = wg[0], w1 = wg[1];
            z[0] += xv * w0.x; z[1] += xv * w0.y; z[2] += xv * w0.z; z[3] += xv * w0.w;
            z[4] += xv * w1.x; z[5] += xv * w1.y; z[6] += xv * w1.z; z[7] += xv * w1.w;
        }
#pragma unroll
        for (int e = 0; e < N_EXP; e++) {
#pragma unroll
            for (int off = 16; off; off >>= 1)
                z[e] += __shfl_xor_sync(0xffffffffu, z[e], off);
        }
        float m = z[0];
#pragma unroll
        for (int e = 1; e < N_EXP; e++) m = fmaxf(m, z[e]);
        float s = 0.f, p[N_EXP];
#pragma unroll
        for (int e = 0; e < N_EXP; e++) { p[e] = expf(z[e] - m); s += p[e]; }
        float inv = 1.f / s;
        if (lane < N_EXP) g_gates[(size_t)warp * N_EXP + lane] = p[lane] * inv;
    } else if (b < NG + NPX) {
        size_t i4 = (size_t)(b - NG) * 256 + tid;
        float4 v = reinterpret_cast<const float4*>(x)[i4];
        reinterpret_cast<uint2*>(g_xhi)[i4] = make_uint2(
            pack_half2(__float2half_rn(v.x), __float2half_rn(v.y)),
            pack_half2(__float2half_rn(v.z), __float2half_rn(v.w)));
    } else {
        size_t i4 = (size_t)(b - NG - NPX) * 256 + tid;
        size_t idx = i4 * 4;
        int e = (int)(idx / ((size_t)O_PAD * D_IN));
        size_t rem = idx % ((size_t)O_PAD * D_IN);
        int o = (int)(rem / D_IN);
        int k = (int)(rem % D_IN);
        float4 v = make_float4(0.f, 0.f, 0.f, 0.f);
        if (o < O_OUT)
            v = *reinterpret_cast<const float4*>(
                expert_w + ((size_t)e * O_OUT + o) * D_IN + k);
        reinterpret_cast<uint2*>(g_whi)[i4] = make_uint2(
            pack_half2(__float2half_rn(v.x), __float2half_rn(v.y)),
            pack_half2(__float2half_rn(v.z), __float2half_rn(v.w)));
    }
}

// ---------------------------------------------------------------------------
// Kernel 2: fused bw + gbw (exact fp32 path, unchanged)
// ---------------------------------------------------------------------------
#define OCH 75
__global__ __launch_bounds__(256) void bw_gbw_kernel(
    const float* __restrict__ expert_bias, const float* __restrict__ expert_w)
{
    const int l = blockIdx.x;
    const int ob4 = blockIdx.y * OCH;
    const int tid = threadIdx.x;

    __shared__ float sbias[N_EXP][D_IN];
    __shared__ float sbw[N_EXP][OCH + 1];

    for (int i = tid; i < N_EXP * D_IN / 4; i += 256) {
        int e = i / (D_IN / 4), kk = i % (D_IN / 4);
        float4 v = *reinterpret_cast<const float4*>(
            expert_bias + ((size_t)e * L_SEQ + l) * D_IN + kk * 4);
        *reinterpret_cast<float4*>(&sbias[e][kk * 4]) = v;
    }
    __syncthreads();

    for (int i = tid; i < N_EXP * OCH; i += 256) {
        int e = i / OCH, oo = i % OCH;
        const float* wr = expert_w + ((size_t)e * O_OUT + ob4 + oo) * D_IN;
        float s = 0.f;
#pragma unroll 4
        for (int k = 0; k < D_IN; k += 4) {
            float4 w4 = *reinterpret_cast<const float4*>(wr + k);
            s += sbias[e][k] * w4.x + sbias[e][k + 1] * w4.y
               + sbias[e][k + 2] * w4.z + sbias[e][k + 3] * w4.w;
        }
        sbw[e][oo] = s;
    }
    __syncthreads();

    for (int i = tid; i < B_TOK * OCH; i += 256) {
        int bb = i / OCH, oo = i % OCH;
        int t = bb * L_SEQ + l;
        const float4* gp = reinterpret_cast<const float4*>(g_gates + (size_t)t * N_EXP);
        float4 ga = gp[0], gb = gp[1];
        float s = ga.x * sbw[0][oo] + ga.y * sbw[1][oo]
                + ga.z * sbw[2][oo] + ga.w * sbw[3][oo]
                + gb.x * sbw[4][oo] + gb.y * sbw[5][oo]
                + gb.z * sbw[6][oo] + gb.w * sbw[7][oo];
        g_gbw[(size_t)t * O_OUT + ob4 + oo] = s;
    }
}

// ---------------------------------------------------------------------------
// Kernel 3: main GEMM. 512 threads, 16 warps (4M x 4N), warp tile 32M x 40N.
// SINGLE fp16 pass: dd_e = Ah * Bh; fold once per (expert, chunk).
// ---------------------------------------------------------------------------
extern __shared__ unsigned char dsmem[];

__global__ __launch_bounds__(512, 1) void moe_hmma_kernel(float* __restrict__ out)
{
    const int tid  = threadIdx.x;
    const int lane = tid & 31;
    const int wid  = tid >> 5;
    const int wm   = wid & 3;
    const int wn   = wid >> 2;
    const int tb   = blockIdx.x * MT;
    const int ob   = blockIdx.y * NT;

    const uint32_t sb   = smem_u32(dsmem);
    const uint32_t A_hi = sb;
    const uint32_t Bbas = sb + OFF_B;
    float* sg = reinterpret_cast<float*>(dsmem + OFF_G);

    const uint32_t laneA  = (uint32_t)(((lane & 7) + ((lane >> 3) & 1) * 8) * RS
                                       + ((lane >> 4) & 1) * 16);
    const uint32_t laneB4 = (uint32_t)(((lane & 7) + ((lane >> 4) & 1) * 8) * RS
                                       + ((lane >> 3) & 1) * 16);
    const int li = lane & 15;
    const uint32_t laneB2 = (uint32_t)((li & 7) * RS + (li >> 3) * 16);

    const int grp  = lane >> 2;
    const int rofs = wm * 32 + grp;

    // stage gates [128 x 8] to smem
#pragma unroll
    for (int t = 0; t < 2; t++) {
        int i = tid + t * 512;
        sg[i] = g_gates[(size_t)(tb + (i >> 3)) * N_EXP + (i & 7)];
    }

    float outacc[2][5][4];
#pragma unroll
    for (int i = 0; i < 2; i++)
#pragma unroll
        for (int j = 0; j < 5; j++)
#pragma unroll
            for (int q = 0; q < 4; q++) outacc[i][j][q] = 0.f;

    for (int c = 0; c < NCHUNK; c++) {
        const int c0 = c * KC;
        __syncthreads();   // previous chunk's compute done (covers sg on c=0)

        // ---- stage A_hi: 1 uint4 per thread ----
        {
            int row = tid >> 2, c8 = tid & 3;
            cp_async16(A_hi + (uint32_t)(row * RS + c8 * 16),
                       g_xhi + (size_t)(tb + row) * D_IN + c0 + c8 * 8);
        }
        // ---- stage B (hi only) for 8 experts: 10 uint4 per thread ----
#pragma unroll
        for (int t = 0; t < 10; t++) {
            int i = tid + t * 512;          // 0..5119
            int e = i / 640;
            int rr = i - e * 640;
            int r = rr >> 2, c8 = rr & 3;
            cp_async16(Bbas + (uint32_t)(e * B_BYTES + r * RS + c8 * 16),
                       g_whi + ((size_t)e * O_PAD + ob + r) * D_IN + c0 + c8 * 8);
        }
        cp_commit_wait0();
        __syncthreads();

#pragma unroll 1
        for (int e = 0; e < N_EXP; e++) {
            const uint32_t Bh = Bbas + (uint32_t)(e * B_BYTES);

            float dd[2][5][4];
#pragma unroll
            for (int i = 0; i < 2; i++)
#pragma unroll
                for (int j = 0; j < 5; j++)
#pragma unroll
                    for (int q = 0; q < 4; q++) dd[i][j][q] = 0.f;

#pragma unroll
            for (int ks = 0; ks < 2; ks++) {
                uint32_t ah[2][4];
#pragma unroll
                for (int mi = 0; mi < 2; mi++)
                    ldsm_x4(ah[mi], A_hi + laneA
                            + (uint32_t)((wm * 32 + mi * 16) * RS + ks * 32));

                uint32_t b4a[4], b4b[4], b2[2];
                ldsm_x4(b4a, Bh + laneB4 + (uint32_t)((wn * 40) * RS + ks * 32));
                ldsm_x4(b4b, Bh + laneB4 + (uint32_t)((wn * 40 + 16) * RS + ks * 32));
                ldsm_x2(b2,  Bh + laneB2 + (uint32_t)((wn * 40 + 32) * RS + ks * 32));
#pragma unroll
                for (int mi = 0; mi < 2; mi++) {
                    mma_f16(dd[mi][0], ah[mi], b4a);
                    mma_f16(dd[mi][1], ah[mi], b4a + 2);
                    mma_f16(dd[mi][2], ah[mi], b4b);
                    mma_f16(dd[mi][3], ah[mi], b4b + 2);
                    mma_f16(dd[mi][4], ah[mi], b2);
                }
            }

            // ---- fold once per (expert, chunk): outacc += g * dd ----
            float g0 = sg[(rofs)      * N_EXP + e];
            float g1 = sg[(rofs + 8)  * N_EXP + e];
            float g2 = sg[(rofs + 16) * N_EXP + e];
            float g3 = sg[(rofs + 24) * N_EXP + e];
#pragma unroll
            for (int nt = 0; nt < 5; nt++) {
                outacc[0][nt][0] += g0 * dd[0][nt][0];
                outacc[0][nt][1] += g0 * dd[0][nt][1];
                outacc[0][nt][2] += g1 * dd[0][nt][2];
                outacc[0][nt][3] += g1 * dd[0][nt][3];
                outacc[1][nt][0] += g2 * dd[1][nt][0];
                outacc[1][nt][1] += g2 * dd[1][nt][1];
                outacc[1][nt][2] += g3 * dd[1][nt][2];
                outacc[1][nt][3] += g3 * dd[1][nt][3];
            }
        }
    }

    // ---- epilogue: out = outacc - gbw ----
#pragma unroll
    for (int mi = 0; mi < 2; mi++) {
        const int t0 = tb + rofs + mi * 16;
#pragma unroll
        for (int nt = 0; nt < 5; nt++) {
            const int o = ob + wn * 40 + nt * 8 + (lane & 3) * 2;
            if (o < O_OUT) {
                {
                    const float2 gb = *reinterpret_cast<const float2*>(
                        g_gbw + (size_t)t0 * O_OUT + o);
                    float2 w = make_float2(outacc[mi][nt][0] - gb.x,
                                           outacc[mi][nt][1] - gb.y);
                    *reinterpret_cast<float2*>(out + (size_t)t0 * O_OUT + o) = w;
                }
                {
                    const int t1 = t0 + 8;
                    const float2 gb = *reinterpret_cast<const float2*>(
                        g_gbw + (size_t)t1 * O_OUT + o);
                    float2 w = make_float2(outacc[mi][nt][2] - gb.x,
                                           outacc[mi][nt][3] - gb.y);
                    *reinterpret_cast<float2*>(out + (size_t)t1 * O_OUT + o) = w;
                }
            }
        }
    }
}

// ---------------------------------------------------------------------------
extern "C" void kernel_launch(void* const* d_in, const int* in_sizes, int n_in,
                              void* d_out, int out_size)
{
    const float* x           = (const float*)d_in[0];
    const float* w_gate      = (const float*)d_in[1];
    const float* expert_w    = (const float*)d_in[2];
    const float* expert_bias = (const float*)d_in[3];
    float* out = (float*)d_out;
    (void)in_sizes; (void)n_in; (void)out_size;

    cudaFuncSetAttribute(moe_hmma_kernel,
                         cudaFuncAttributeMaxDynamicSharedMemorySize, SMEM_MAIN);

    prologue_kernel<<<NG + NPX + NPW, 256>>>(x, w_gate, expert_w);
    bw_gbw_kernel<<<dim3(L_SEQ, O_OUT / OCH), 256>>>(expert_bias, expert_w);
    moe_hmma_kernel<<<dim3(T_TOK / MT, O_PAD / NT), 512, SMEM_MAIN>>>(out);
}